// round 10
// baseline (speedup 1.0000x reference)
#include <cuda_runtime.h>
#include <stdint.h>

// LayoutBBox: in (B,12,64) f32 -> out (B,8,128,128) f32
// out[b,c,h,w] = max_n xy[n,h,w]*cls[n,c], xy = max(lx(w)*gx(h), ly(h)*gy(w))
// prep: exact bitmasks + packed per-box profile tables (wtab/htab2) + classes.
// main: 2 rows/thread (fixed pair), table-driven trips (2 LDG + LDS + flops),
//       interleaved pair assignment for CTA balance, PDL overlap.

constexpr int Wd   = 128;
constexpr int Hd   = 128;
constexpr int NP   = Hd / 2;        // 64 row pairs
constexpr int NUMB = 64;
constexpr int NCLS = 8;
constexpr int INCH = 12;
constexpr int MAXB = 16;

using u64 = unsigned long long;

__device__ __forceinline__ u64 pk(float lo, float hi) {
    u64 r; asm("mov.b64 %0,{%1,%2};" : "=l"(r) : "f"(lo), "f"(hi)); return r;
}
__device__ __forceinline__ void upk(float& lo, float& hi, u64 v) {
    asm("mov.b64 {%0,%1},%2;" : "=f"(lo), "=f"(hi) : "l"(v));
}
__device__ __forceinline__ u64 pmul(u64 a, u64 b) {
    u64 r; asm("mul.rn.f32x2 %0,%1,%2;" : "=l"(r) : "l"(a), "l"(b)); return r;
}

__device__ ulonglong2 g_cmask[MAXB][Wd];        // (Mlx, Mgw) per (b,w)
__device__ ulonglong2 g_rmask2[MAXB][NP];       // pair-union (Mgh, Mly)
__device__ ulonglong2 g_ca[MAXB][NUMB];         // packed (c0,c1),(c2,c3)
__device__ ulonglong2 g_cb[MAXB][NUMB];         // packed (c4,c5),(c6,c7)
__device__ u64        g_wtab[MAXB][NUMB][Wd];   // packed (lx, gy)
__device__ ulonglong2 g_htab2[MAXB][NP][NUMB];  // packed (gx0,ly0),(gx1,ly1)

// ---------------- prep kernel: grid (2, B), block 1024 ----------------
__global__ void prep_kernel(const float* __restrict__ in)
{
    const int b   = blockIdx.y;
    const int tid = threadIdx.x;
    const float* base = in + (size_t)b * INCH * NUMB;
    __shared__ float2 sxy[NUMB];

    if (blockIdx.x == 0) {
        // ---- x-side: classes, x1/x2, column masks, wtab ----
        if (tid < NUMB) {
            float xc = base[0 * NUMB + tid] * 128.0f;
            float bw = base[2 * NUMB + tid] * 128.0f;
            sxy[tid] = make_float2(xc - 0.5f * bw, xc + 0.5f * bw);
            ulonglong2 ca, cb;
            ca.x = pk(base[4 * NUMB + tid],  base[5 * NUMB + tid]);
            ca.y = pk(base[6 * NUMB + tid],  base[7 * NUMB + tid]);
            cb.x = pk(base[8 * NUMB + tid],  base[9 * NUMB + tid]);
            cb.y = pk(base[10 * NUMB + tid], base[11 * NUMB + tid]);
            g_ca[b][tid] = ca;
            g_cb[b][tid] = cb;
        }
        __syncthreads();
        {   // column masks, byte-parallel (1024 slots)
            int w = tid >> 3, j = tid & 7;
            float wf = (float)w;
            unsigned blx = 0, bgw = 0;
            #pragma unroll
            for (int k = 0; k < 8; k++) {
                float2 x = sxy[8 * j + k];
                if (fabsf(wf - x.x) < 1.0f || fabsf(x.y - wf) < 1.0f) blx |= 1u << k;
                if (wf > x.x && wf < x.y)                             bgw |= 1u << k;
            }
            unsigned char* dst = (unsigned char*)&g_cmask[b][w];
            dst[j]     = (unsigned char)blx;
            dst[8 + j] = (unsigned char)bgw;
        }
        // wtab: 8192 entries, 8 per thread
        #pragma unroll
        for (int t = 0; t < 8; t++) {
            int i = tid + t * 1024;
            int n = i >> 7, w = i & 127;
            float2 x = sxy[n];
            float wf = (float)w;
            float dx1 = wf - x.x, dx2 = x.y - wf;
            float lx = fmaxf(0.0f, fmaxf(1.0f - fabsf(dx1), 1.0f - fabsf(dx2)));
            float gy = __saturatef(dx1) * __saturatef(dx2);
            g_wtab[b][n][w] = pk(lx, gy);
        }
    } else {
        // ---- y-side: y1/y2, pair-union row masks, htab2 ----
        if (tid < NUMB) {
            float yc = base[1 * NUMB + tid] * 128.0f;
            float bh = base[3 * NUMB + tid] * 128.0f;
            sxy[tid] = make_float2(yc - 0.5f * bh, yc + 0.5f * bh);
        }
        __syncthreads();
        if (tid < NP * 8) {   // pair-union row masks (512 slots)
            int p = tid >> 3, j = tid & 7;
            float hf0 = (float)(2 * p);
            float hf1 = hf0 + 1.0f;
            unsigned bgh = 0, bly = 0;
            #pragma unroll
            for (int k = 0; k < 8; k++) {
                float2 y = sxy[8 * j + k];
                bool g0 = (hf0 > y.x && hf0 < y.y);
                bool g1 = (hf1 > y.x && hf1 < y.y);
                if (g0 || g1) bgh |= 1u << k;
                bool l0 = (fabsf(hf0 - y.x) < 1.0f || fabsf(y.y - hf0) < 1.0f);
                bool l1 = (fabsf(hf1 - y.x) < 1.0f || fabsf(y.y - hf1) < 1.0f);
                if (l0 || l1) bly |= 1u << k;
            }
            unsigned char* dst = (unsigned char*)&g_rmask2[b][p];
            dst[j]     = (unsigned char)bgh;
            dst[8 + j] = (unsigned char)bly;
        }
        // htab2: 4096 entries, 4 per thread
        #pragma unroll
        for (int t = 0; t < 4; t++) {
            int i = tid + t * 1024;
            int p = i >> 6, n = i & 63;
            float2 y = sxy[n];
            float hf0 = (float)(2 * p);
            float hf1 = hf0 + 1.0f;
            float dy1 = hf0 - y.x, dy2 = y.y - hf0;
            float gx0 = __saturatef(dy1) * __saturatef(dy2);
            float ly0 = fmaxf(0.0f, fmaxf(1.0f - fabsf(dy1), 1.0f - fabsf(dy2)));
            dy1 = hf1 - y.x; dy2 = y.y - hf1;
            float gx1 = __saturatef(dy1) * __saturatef(dy2);
            float ly1 = fmaxf(0.0f, fmaxf(1.0f - fabsf(dy1), 1.0f - fabsf(dy2)));
            ulonglong2 e;
            e.x = pk(gx0, ly0);
            e.y = pk(gx1, ly1);
            g_htab2[b][p][n] = e;
        }
    }
    asm volatile("griddepcontrol.launch_dependents;" ::: "memory");
}

// -------- main kernel: grid (NP/2, B), block (128, 2); one row-pair/thread ----
__global__ __launch_bounds__(256)
void layout_bbox_main(float* __restrict__ out)
{
    __shared__ ulonglong2 sca[NUMB];
    __shared__ ulonglong2 scb[NUMB];

    const int tx  = threadIdx.x;                      // w
    const int ty  = threadIdx.y;
    const int tid = ty * Wd + tx;
    const int b   = blockIdx.y;
    const int p   = blockIdx.x + ty * (NP / 2);       // interleaved pair index
    const int h0  = 2 * p;

    asm volatile("griddepcontrol.wait;" ::: "memory");

    if (tid < NUMB)            sca[tid]        = g_ca[b][tid];
    else if (tid < 2 * NUMB)   scb[tid - NUMB] = g_cb[b][tid - NUMB];

    const ulonglong2 cm  = g_cmask[b][tx];
    const ulonglong2 rmu = g_rmask2[b][p];
    u64 m = (cm.x & rmu.x) | (cm.y & rmu.y);          // exact pair-union set

    __syncthreads();

    const ulonglong2* __restrict__ ht = g_htab2[b][p];

    float a0 = 0.f, a1 = 0.f, a2 = 0.f, a3 = 0.f;
    float a4 = 0.f, a5 = 0.f, a6 = 0.f, a7 = 0.f;
    float b0 = 0.f, b1 = 0.f, b2 = 0.f, b3 = 0.f;
    float b4 = 0.f, b5 = 0.f, b6 = 0.f, b7 = 0.f;

    while (m) {                                       // divergent per-lane loop
        int n = __ffsll((long long)m) - 1;
        m &= m - 1;
        u64        wv = g_wtab[b][n][tx];             // (lx, gy)   LDG.64
        ulonglong2 hv = ht[n];                        // (gx,ly)x2  LDG.128

        float t0, t1;
        upk(t0, t1, pmul(wv, hv.x));                  // (lx*gx0, gy*ly0)
        float xy0 = fmaxf(t0, t1);
        upk(t0, t1, pmul(wv, hv.y));                  // (lx*gx1, gy*ly1)
        float xy1 = fmaxf(t0, t1);

        u64 x0 = pk(xy0, xy0);
        u64 x1 = pk(xy1, xy1);
        ulonglong2 ca = sca[n];                       // LDS.128
        ulonglong2 cb = scb[n];                       // LDS.128
        float p0, p1;
        upk(p0, p1, pmul(x0, ca.x)); a0 = fmaxf(a0, p0); a1 = fmaxf(a1, p1);
        upk(p0, p1, pmul(x0, ca.y)); a2 = fmaxf(a2, p0); a3 = fmaxf(a3, p1);
        upk(p0, p1, pmul(x0, cb.x)); a4 = fmaxf(a4, p0); a5 = fmaxf(a5, p1);
        upk(p0, p1, pmul(x0, cb.y)); a6 = fmaxf(a6, p0); a7 = fmaxf(a7, p1);
        upk(p0, p1, pmul(x1, ca.x)); b0 = fmaxf(b0, p0); b1 = fmaxf(b1, p1);
        upk(p0, p1, pmul(x1, ca.y)); b2 = fmaxf(b2, p0); b3 = fmaxf(b3, p1);
        upk(p0, p1, pmul(x1, cb.x)); b4 = fmaxf(b4, p0); b5 = fmaxf(b5, p1);
        upk(p0, p1, pmul(x1, cb.y)); b6 = fmaxf(b6, p0); b7 = fmaxf(b7, p1);
    }

    float* o = out + (((size_t)b * NCLS) * Hd + h0) * Wd + tx;
    const int cs = Hd * Wd;
    o[0 * cs] = a0; o[1 * cs] = a1; o[2 * cs] = a2; o[3 * cs] = a3;
    o[4 * cs] = a4; o[5 * cs] = a5; o[6 * cs] = a6; o[7 * cs] = a7;
    o += Wd;
    o[0 * cs] = b0; o[1 * cs] = b1; o[2 * cs] = b2; o[3 * cs] = b3;
    o[4 * cs] = b4; o[5 * cs] = b5; o[6 * cs] = b6; o[7 * cs] = b7;
}

extern "C" void kernel_launch(void* const* d_in, const int* in_sizes, int n_in,
                              void* d_out, int out_size)
{
    const float* in = (const float*)d_in[0];
    float* out = (float*)d_out;
    int B = in_sizes[0] / (INCH * NUMB);   // 16

    prep_kernel<<<dim3(2, B), 1024>>>(in);

    cudaLaunchConfig_t cfg = {};
    cfg.gridDim  = dim3(NP / 2, B);        // (32, B) = 512 CTAs
    cfg.blockDim = dim3(Wd, 2);            // 128 x 2 = 256 threads
    cudaLaunchAttribute attr[1];
    attr[0].id = cudaLaunchAttributeProgrammaticStreamSerialization;
    attr[0].val.programmaticStreamSerializationAllowed = 1;
    cfg.attrs = attr;
    cfg.numAttrs = 1;
    cudaLaunchKernelEx(&cfg, layout_bbox_main, out);
}

// round 11
// speedup vs baseline: 1.1631x; 1.1631x over previous
#include <cuda_runtime.h>
#include <stdint.h>

// LayoutBBox: in (B,12,64) f32 -> out (B,8,128,128) f32
// out[b,c,h,w] = max_n xy[n,h,w]*cls[n,c], xy = max(lx(w)*gx(h), ly(h)*gy(w))
// prep: exact per-(b,w)/(b,h) nonzero bitmasks + packed box records (PDL producer)
// main: 1 row/thread (8192 warps, high occupancy), per-lane exact mask,
//       records staged in shared memory, inline profile math.

constexpr int Wd   = 128;
constexpr int Hd   = 128;
constexpr int NUMB = 64;
constexpr int NCLS = 8;
constexpr int INCH = 12;
constexpr int MAXB = 16;

using u64 = unsigned long long;

__device__ __forceinline__ u64 pk(float lo, float hi) {
    u64 r; asm("mov.b64 %0,{%1,%2};" : "=l"(r) : "f"(lo), "f"(hi)); return r;
}
__device__ __forceinline__ void upk(float& lo, float& hi, u64 v) {
    asm("mov.b64 {%0,%1},%2;" : "=f"(lo), "=f"(hi) : "l"(v));
}
__device__ __forceinline__ u64 pmul(u64 a, u64 b) {
    u64 r; asm("mul.rn.f32x2 %0,%1,%2;" : "=l"(r) : "l"(a), "l"(b)); return r;
}

__device__ ulonglong2 g_cmask[MAXB][Wd];   // (Mlx, Mgw) per (b,w)
__device__ ulonglong2 g_rmask[MAXB][Hd];   // (Mgh, Mly) per (b,h)
__device__ float4     g_p [MAXB][NUMB];    // x1, x2, y1, y2
__device__ ulonglong2 g_ca[MAXB][NUMB];    // packed (c0,c1),(c2,c3)
__device__ ulonglong2 g_cb[MAXB][NUMB];    // packed (c4,c5),(c6,c7)

// ---------------- prep kernel: grid (2, B), block 1024 ----------------
__global__ void prep_kernel(const float* __restrict__ in)
{
    const int b   = blockIdx.y;
    const int tid = threadIdx.x;
    const float* base = in + (size_t)b * INCH * NUMB;

    if (blockIdx.x == 0) {
        if (tid < NUMB) {
            float xc = base[0 * NUMB + tid] * 128.0f;
            float yc = base[1 * NUMB + tid] * 128.0f;
            float bw = base[2 * NUMB + tid] * 128.0f;
            float bh = base[3 * NUMB + tid] * 128.0f;
            g_p[b][tid] = make_float4(xc - 0.5f * bw, xc + 0.5f * bw,
                                      yc - 0.5f * bh, yc + 0.5f * bh);
            ulonglong2 ca, cb;
            ca.x = pk(base[4 * NUMB + tid],  base[5 * NUMB + tid]);
            ca.y = pk(base[6 * NUMB + tid],  base[7 * NUMB + tid]);
            cb.x = pk(base[8 * NUMB + tid],  base[9 * NUMB + tid]);
            cb.y = pk(base[10 * NUMB + tid], base[11 * NUMB + tid]);
            g_ca[b][tid] = ca;
            g_cb[b][tid] = cb;
        }
        {   // column masks, byte-parallel (1024 slots)
            int w = tid >> 3, j = tid & 7;
            float wf = (float)w;
            unsigned blx = 0, bgw = 0;
            #pragma unroll
            for (int k = 0; k < 8; k++) {
                int n = 8 * j + k;
                float xc = base[0 * NUMB + n] * 128.0f;
                float bw = base[2 * NUMB + n] * 128.0f;
                float x1 = xc - 0.5f * bw, x2 = xc + 0.5f * bw;
                if (fabsf(wf - x1) < 1.0f || fabsf(x2 - wf) < 1.0f) blx |= 1u << k;
                if (wf > x1 && wf < x2)                             bgw |= 1u << k;
            }
            unsigned char* dst = (unsigned char*)&g_cmask[b][w];
            dst[j]     = (unsigned char)blx;
            dst[8 + j] = (unsigned char)bgw;
        }
    } else {
        // row masks (1024 slots)
        int h = tid >> 3, j = tid & 7;
        float hf = (float)h;
        unsigned bgh = 0, bly = 0;
        #pragma unroll
        for (int k = 0; k < 8; k++) {
            int n = 8 * j + k;
            float yc = base[1 * NUMB + n] * 128.0f;
            float bh = base[3 * NUMB + n] * 128.0f;
            float y1 = yc - 0.5f * bh, y2 = yc + 0.5f * bh;
            if (hf > y1 && hf < y2)                             bgh |= 1u << k;
            if (fabsf(hf - y1) < 1.0f || fabsf(y2 - hf) < 1.0f) bly |= 1u << k;
        }
        unsigned char* dst = (unsigned char*)&g_rmask[b][h];
        dst[j]     = (unsigned char)bgh;
        dst[8 + j] = (unsigned char)bly;
    }
    asm volatile("griddepcontrol.launch_dependents;" ::: "memory");
}

// -------- main kernel: grid (Hd/4, B), block (128, 4); 1 row/thread --------
__global__ __launch_bounds__(512)
void layout_bbox_main(float* __restrict__ out)
{
    __shared__ float4     sp [NUMB];
    __shared__ ulonglong2 sca[NUMB];
    __shared__ ulonglong2 scb[NUMB];

    const int tx  = threadIdx.x;                      // w
    const int ty  = threadIdx.y;
    const int tid = ty * Wd + tx;
    const int b   = blockIdx.y;
    const int h   = blockIdx.x * 4 + ty;
    const float wf = (float)tx;
    const float hf = (float)h;

    asm volatile("griddepcontrol.wait;" ::: "memory");

    // parallel staging: 192 threads, one record-piece each
    if (tid < NUMB)                sp [tid]            = g_p [b][tid];
    else if (tid < 2 * NUMB)       sca[tid - NUMB]     = g_ca[b][tid - NUMB];
    else if (tid < 3 * NUMB)       scb[tid - 2 * NUMB] = g_cb[b][tid - 2 * NUMB];

    const ulonglong2 cm = g_cmask[b][tx];
    const ulonglong2 rm = g_rmask[b][h];
    u64 m = (cm.x & rm.x) | (cm.y & rm.y);            // exact per-pixel set

    __syncthreads();

    float a0 = 0.f, a1 = 0.f, a2 = 0.f, a3 = 0.f;
    float a4 = 0.f, a5 = 0.f, a6 = 0.f, a7 = 0.f;

    while (m) {                                       // divergent per-lane loop
        int n = __ffsll((long long)m) - 1;
        m &= m - 1;
        float4 p = sp[n];                             // LDS.128, scattered

        float dx1 = wf - p.x, dx2 = p.y - wf;
        float lx = fmaxf(0.0f, fmaxf(1.0f - fabsf(dx1), 1.0f - fabsf(dx2)));
        float gy = __saturatef(dx1) * __saturatef(dx2);
        float dy1 = hf - p.z, dy2 = p.w - hf;
        float gx = __saturatef(dy1) * __saturatef(dy2);
        float ly = fmaxf(0.0f, fmaxf(1.0f - fabsf(dy1), 1.0f - fabsf(dy2)));
        float xy = fmaxf(lx * gx, ly * gy);

        u64 xyp = pk(xy, xy);
        ulonglong2 ca = sca[n];                       // LDS.128
        ulonglong2 cb = scb[n];                       // LDS.128
        float p0, p1;
        upk(p0, p1, pmul(xyp, ca.x)); a0 = fmaxf(a0, p0); a1 = fmaxf(a1, p1);
        upk(p0, p1, pmul(xyp, ca.y)); a2 = fmaxf(a2, p0); a3 = fmaxf(a3, p1);
        upk(p0, p1, pmul(xyp, cb.x)); a4 = fmaxf(a4, p0); a5 = fmaxf(a5, p1);
        upk(p0, p1, pmul(xyp, cb.y)); a6 = fmaxf(a6, p0); a7 = fmaxf(a7, p1);
    }

    float* o = out + (((size_t)b * NCLS) * Hd + h) * Wd + tx;
    const int cs = Hd * Wd;
    o[0 * cs] = a0; o[1 * cs] = a1; o[2 * cs] = a2; o[3 * cs] = a3;
    o[4 * cs] = a4; o[5 * cs] = a5; o[6 * cs] = a6; o[7 * cs] = a7;
}

extern "C" void kernel_launch(void* const* d_in, const int* in_sizes, int n_in,
                              void* d_out, int out_size)
{
    const float* in = (const float*)d_in[0];
    float* out = (float*)d_out;
    int B = in_sizes[0] / (INCH * NUMB);   // 16

    prep_kernel<<<dim3(2, B), 1024>>>(in);

    cudaLaunchConfig_t cfg = {};
    cfg.gridDim  = dim3(Hd / 4, B);        // (32, B) = 512 CTAs
    cfg.blockDim = dim3(Wd, 4);            // 128 x 4 = 512 threads
    cudaLaunchAttribute attr[1];
    attr[0].id = cudaLaunchAttributeProgrammaticStreamSerialization;
    attr[0].val.programmaticStreamSerializationAllowed = 1;
    cfg.attrs = attr;
    cfg.numAttrs = 1;
    cudaLaunchKernelEx(&cfg, layout_bbox_main, out);
}